// round 1
// baseline (speedup 1.0000x reference)
#include <cuda_runtime.h>
#include <math.h>

#define HD 256      // hidden dim
#define BB 2        // batch
#define LL 512      // seq len (L1 == L2)
#define NHEAD 8
#define DHEAD 32

// ---------------- scratch (device globals; no allocation) ----------------
__device__ float g_q [BB*LL*HD];                 // 1 MB
__device__ float g_k [BB*LL*HD];                 // 1 MB
__device__ float g_h1[BB*LL*HD];                 // 1 MB (includes +b1)
__device__ float g_h2[BB*LL*HD];                 // 1 MB
__device__ float g_logits[(size_t)BB*NHEAD*LL*LL]; // 16 MB

// =========================================================================
// K1: projections.  job z: 0=q(e1,Wq,bq) 1=k(e2,Wk,bk) 2=h1(e1,W1a,b1) 3=h2(e2,W1b,0)
// C[m,o] = sum_c A[m,c]*W[o*ldw + c] (+ bias[o]);  M=1024, N=256, K=256
// =========================================================================
__global__ __launch_bounds__(256) void proj_kernel(
    const float* __restrict__ e1, const float* __restrict__ e2,
    const float* __restrict__ ipw, const float* __restrict__ ipb,
    const float* __restrict__ W1,  const float* __restrict__ b1)
{
    const int job = blockIdx.z;
    const float* A; const float* W; const float* bias; int ldw; float* C;
    if (job == 0)      { A = e1; W = ipw;           bias = ipb;      ldw = HD;   C = g_q;  }
    else if (job == 1) { A = e2; W = ipw + HD*HD;   bias = ipb + HD; ldw = HD;   C = g_k;  }
    else if (job == 2) { A = e1; W = W1;            bias = b1;       ldw = 2*HD; C = g_h1; }
    else               { A = e2; W = W1 + HD;       bias = nullptr;  ldw = 2*HD; C = g_h2; }

    const int K  = HD;
    const int i0 = blockIdx.y * 64;
    const int j0 = blockIdx.x * 64;

    __shared__ float sA[32][65];
    __shared__ float sW[32][65];

    const int tid = threadIdx.x;
    const int tx = tid & 15, ty = tid >> 4;

    float acc[4][4] = {};

    for (int k0 = 0; k0 < K; k0 += 32) {
#pragma unroll
        for (int r = 0; r < 8; r++) {
            int idx = r * 256 + tid;
            int m = idx >> 5, kk = idx & 31;
            sA[kk][m] = A[(size_t)(i0 + m) * K   + k0 + kk];
            sW[kk][m] = W[(size_t)(j0 + m) * ldw + k0 + kk];
        }
        __syncthreads();
#pragma unroll
        for (int kk = 0; kk < 32; kk++) {
            float a[4], w[4];
#pragma unroll
            for (int u = 0; u < 4; u++) { a[u] = sA[kk][ty*4 + u]; w[u] = sW[kk][tx*4 + u]; }
#pragma unroll
            for (int u = 0; u < 4; u++)
#pragma unroll
                for (int v = 0; v < 4; v++)
                    acc[u][v] = fmaf(a[u], w[v], acc[u][v]);
        }
        __syncthreads();
    }

#pragma unroll
    for (int u = 0; u < 4; u++) {
        int row = i0 + ty*4 + u;
#pragma unroll
        for (int v = 0; v < 4; v++) {
            int col = j0 + tx*4 + v;
            float r = acc[u][v] + (bias ? bias[col] : 0.0f);
            C[(size_t)row * HD + col] = r;
        }
    }
}

// =========================================================================
// K2: logits[b,h,i,j] = (1/sqrt(32)) * sum_d q[b,i,h*32+d]*k[b,j,h*32+d]
// grid (8,8,16): z = b*8+h ; 64x64 tile, K=32
// =========================================================================
__global__ __launch_bounds__(256) void logits_kernel()
{
    const int bh = blockIdx.z;
    const int b  = bh >> 3, h = bh & 7;
    const float* Q  = g_q + (size_t)b * LL * HD + h * DHEAD;
    const float* Kp = g_k + (size_t)b * LL * HD + h * DHEAD;
    float* C = g_logits + (size_t)bh * LL * LL;

    const int i0 = blockIdx.y * 64;
    const int j0 = blockIdx.x * 64;

    __shared__ float sA[32][65];
    __shared__ float sW[32][65];

    const int tid = threadIdx.x;
    const int tx = tid & 15, ty = tid >> 4;

#pragma unroll
    for (int r = 0; r < 8; r++) {
        int idx = r * 256 + tid;
        int m = idx >> 5, kk = idx & 31;
        sA[kk][m] = Q [(size_t)(i0 + m) * HD + kk];
        sW[kk][m] = Kp[(size_t)(j0 + m) * HD + kk];
    }
    __syncthreads();

    float acc[4][4] = {};
#pragma unroll
    for (int kk = 0; kk < 32; kk++) {
        float a[4], w[4];
#pragma unroll
        for (int u = 0; u < 4; u++) { a[u] = sA[kk][ty*4 + u]; w[u] = sW[kk][tx*4 + u]; }
#pragma unroll
        for (int u = 0; u < 4; u++)
#pragma unroll
            for (int v = 0; v < 4; v++)
                acc[u][v] = fmaf(a[u], w[v], acc[u][v]);
    }

    const float scale = 0.1767766952966369f; // 1/sqrt(32)
#pragma unroll
    for (int u = 0; u < 4; u++) {
        int row = i0 + ty*4 + u;
#pragma unroll
        for (int v = 0; v < 4; v++)
            C[(size_t)row * LL + (j0 + tx*4 + v)] = acc[u][v] * scale;
    }
}

// =========================================================================
// K3: per (b,i): softmax over j for each head, average heads -> out[0 .. B*L*L)
// grid 1024 blocks of 256 threads; each thread handles j = t and t+256
// =========================================================================
__global__ __launch_bounds__(256) void softmax_mean_kernel(float* __restrict__ out)
{
    const int b = blockIdx.x >> 9;
    const int i = blockIdx.x & 511;
    const int t = threadIdx.x;

    __shared__ float acc[512];
    __shared__ float red[8];
    __shared__ float bcast;

    acc[t] = 0.0f; acc[t + 256] = 0.0f;

    for (int h = 0; h < 8; h++) {
        const float* row = g_logits + ((size_t)(b*8 + h) * LL + i) * LL;
        float v0 = row[t], v1 = row[t + 256];

        // block max
        float m = fmaxf(v0, v1);
#pragma unroll
        for (int o = 16; o; o >>= 1) m = fmaxf(m, __shfl_xor_sync(0xffffffffu, m, o));
        if ((t & 31) == 0) red[t >> 5] = m;
        __syncthreads();
        if (t < 8) {
            float mm = red[t];
#pragma unroll
            for (int o = 4; o; o >>= 1) mm = fmaxf(mm, __shfl_xor_sync(0xffu, mm, o));
            if (t == 0) bcast = mm;
        }
        __syncthreads();
        const float mx = bcast;

        float e0 = __expf(v0 - mx), e1 = __expf(v1 - mx);

        // block sum
        float s = e0 + e1;
#pragma unroll
        for (int o = 16; o; o >>= 1) s += __shfl_xor_sync(0xffffffffu, s, o);
        if ((t & 31) == 0) red[t >> 5] = s;
        __syncthreads();
        if (t < 8) {
            float ss = red[t];
#pragma unroll
            for (int o = 4; o; o >>= 1) ss += __shfl_xor_sync(0xffu, ss, o);
            if (t == 0) bcast = ss;
        }
        __syncthreads();
        const float inv = 1.0f / bcast;

        acc[t]       += e0 * inv;
        acc[t + 256] += e1 * inv;
    }

    const size_t o = ((size_t)b * LL + i) * LL;
    out[o + t]       = acc[t]       * 0.125f;
    out[o + t + 256] = acc[t + 256] * 0.125f;
}

// =========================================================================
// K4: match_scores[b,i,j] = sigmoid( sum_c relu(h1[b,i,c] + h2[b,j,c]) * w2[c] + b2 )
// (b1 already folded into h1). grid (8,8,2), 64x64 tiles, 4x4 per thread.
// =========================================================================
__global__ __launch_bounds__(256) void match_kernel(
    const float* __restrict__ W2, const float* __restrict__ b2,
    float* __restrict__ out)
{
    const int b  = blockIdx.z;
    const int i0 = blockIdx.y * 64;
    const int j0 = blockIdx.x * 64;

    const float* A  = g_h1 + (size_t)b * LL * HD;
    const float* Bm = g_h2 + (size_t)b * LL * HD;

    __shared__ float sA[32][65];
    __shared__ float sB[32][65];
    __shared__ float sw2[32];

    const int tid = threadIdx.x;
    const int tx = tid & 15, ty = tid >> 4;

    float acc[4][4] = {};

    for (int k0 = 0; k0 < HD; k0 += 32) {
#pragma unroll
        for (int r = 0; r < 8; r++) {
            int idx = r * 256 + tid;
            int m = idx >> 5, kk = idx & 31;
            sA[kk][m] = A [(size_t)(i0 + m) * HD + k0 + kk];
            sB[kk][m] = Bm[(size_t)(j0 + m) * HD + k0 + kk];
        }
        if (tid < 32) sw2[tid] = W2[k0 + tid];
        __syncthreads();

#pragma unroll
        for (int kk = 0; kk < 32; kk++) {
            const float w = sw2[kk];
            float a[4], bb[4];
#pragma unroll
            for (int u = 0; u < 4; u++) { a[u] = sA[kk][ty*4 + u]; bb[u] = sB[kk][tx*4 + u]; }
#pragma unroll
            for (int u = 0; u < 4; u++)
#pragma unroll
                for (int v = 0; v < 4; v++)
                    acc[u][v] = fmaf(fmaxf(a[u] + bb[v], 0.0f), w, acc[u][v]);
        }
        __syncthreads();
    }

    const float bias2 = b2[0];
    const size_t base = (size_t)BB * LL * LL + (size_t)b * LL * LL;
#pragma unroll
    for (int u = 0; u < 4; u++) {
        int row = i0 + ty*4 + u;
#pragma unroll
        for (int v = 0; v < 4; v++) {
            float x = acc[u][v] + bias2;
            out[base + (size_t)row * LL + (j0 + tx*4 + v)] = 1.0f / (1.0f + __expf(-x));
        }
    }
}

// =========================================================================
extern "C" void kernel_launch(void* const* d_in, const int* in_sizes, int n_in,
                              void* d_out, int out_size)
{
    const float* e1  = (const float*)d_in[0];  // (B,L1,H)
    const float* e2  = (const float*)d_in[1];  // (B,L2,H)
    const float* ipw = (const float*)d_in[2];  // (3H,H)
    const float* ipb = (const float*)d_in[3];  // (3H,)
    const float* W1  = (const float*)d_in[4];  // (H,2H)
    const float* b1  = (const float*)d_in[5];  // (H,)
    const float* W2  = (const float*)d_in[6];  // (1,H)
    const float* b2  = (const float*)d_in[7];  // (1,)
    float* out = (float*)d_out;                // [attn (B,L1,L2)] ++ [match (B,L1,L2)]

    proj_kernel   <<<dim3(HD/64, (BB*LL)/64, 4), 256>>>(e1, e2, ipw, ipb, W1, b1);
    logits_kernel <<<dim3(LL/64, LL/64, BB*NHEAD), 256>>>();
    softmax_mean_kernel<<<BB*LL, 256>>>(out);
    match_kernel  <<<dim3(LL/64, LL/64, BB), 256>>>(W2, b2, out);
}

// round 3
// speedup vs baseline: 1.1345x; 1.1345x over previous
#include <cuda_runtime.h>
#include <math.h>

#define HD 256      // hidden dim
#define BB 2        // batch
#define LL 512      // seq len (L1 == L2)
#define NHEAD 8
#define DHEAD 32

// ---------------- scratch (device globals; no allocation) ----------------
__device__ float g_q [BB*LL*HD];                 // 1 MB
__device__ float g_k [BB*LL*HD];                 // 1 MB
__device__ float g_h1[BB*LL*HD];                 // 1 MB (includes +b1)
__device__ float g_h2[BB*LL*HD];                 // 1 MB
__device__ float g_logits[(size_t)BB*NHEAD*LL*LL]; // 16 MB

// =========================================================================
// K1: projections.  job z: 0=q(e1,Wq,bq) 1=k(e2,Wk,bk) 2=h1(e1,W1a,b1) 3=h2(e2,W1b,0)
// C[m,o] = sum_c A[m,c]*W[o*ldw + c] (+ bias[o]);  M=1024, N=256, K=256
// =========================================================================
__global__ __launch_bounds__(256) void proj_kernel(
    const float* __restrict__ e1, const float* __restrict__ e2,
    const float* __restrict__ ipw, const float* __restrict__ ipb,
    const float* __restrict__ W1,  const float* __restrict__ b1)
{
    const int job = blockIdx.z;
    const float* A; const float* W; const float* bias; int ldw; float* C;
    if (job == 0)      { A = e1; W = ipw;           bias = ipb;      ldw = HD;   C = g_q;  }
    else if (job == 1) { A = e2; W = ipw + HD*HD;   bias = ipb + HD; ldw = HD;   C = g_k;  }
    else if (job == 2) { A = e1; W = W1;            bias = b1;       ldw = 2*HD; C = g_h1; }
    else               { A = e2; W = W1 + HD;       bias = nullptr;  ldw = 2*HD; C = g_h2; }

    const int K  = HD;
    const int i0 = blockIdx.y * 64;
    const int j0 = blockIdx.x * 64;

    __shared__ float sA[32][65];
    __shared__ float sW[32][65];

    const int tid = threadIdx.x;
    const int tx = tid & 15, ty = tid >> 4;

    float acc[4][4] = {};

    for (int k0 = 0; k0 < K; k0 += 32) {
#pragma unroll
        for (int r = 0; r < 8; r++) {
            int idx = r * 256 + tid;
            int m = idx >> 5, kk = idx & 31;
            sA[kk][m] = A[(size_t)(i0 + m) * K   + k0 + kk];
            sW[kk][m] = W[(size_t)(j0 + m) * ldw + k0 + kk];
        }
        __syncthreads();
#pragma unroll
        for (int kk = 0; kk < 32; kk++) {
            float a[4], w[4];
#pragma unroll
            for (int u = 0; u < 4; u++) { a[u] = sA[kk][ty*4 + u]; w[u] = sW[kk][tx*4 + u]; }
#pragma unroll
            for (int u = 0; u < 4; u++)
#pragma unroll
                for (int v = 0; v < 4; v++)
                    acc[u][v] = fmaf(a[u], w[v], acc[u][v]);
        }
        __syncthreads();
    }

#pragma unroll
    for (int u = 0; u < 4; u++) {
        int row = i0 + ty*4 + u;
#pragma unroll
        for (int v = 0; v < 4; v++) {
            int col = j0 + tx*4 + v;
            float r = acc[u][v] + (bias ? bias[col] : 0.0f);
            C[(size_t)row * HD + col] = r;
        }
    }
}

// =========================================================================
// K2: logits[b,h,i,j] = (1/sqrt(32)) * sum_d q[b,i,h*32+d]*k[b,j,h*32+d]
// grid (8,8,16): z = b*8+h ; 64x64 tile, K=32
// =========================================================================
__global__ __launch_bounds__(256) void logits_kernel()
{
    const int bh = blockIdx.z;
    const int b  = bh >> 3, h = bh & 7;
    const float* Q  = g_q + (size_t)b * LL * HD + h * DHEAD;
    const float* Kp = g_k + (size_t)b * LL * HD + h * DHEAD;
    float* C = g_logits + (size_t)bh * LL * LL;

    const int i0 = blockIdx.y * 64;
    const int j0 = blockIdx.x * 64;

    __shared__ float sA[32][65];
    __shared__ float sW[32][65];

    const int tid = threadIdx.x;
    const int tx = tid & 15, ty = tid >> 4;

#pragma unroll
    for (int r = 0; r < 8; r++) {
        int idx = r * 256 + tid;
        int m = idx >> 5, kk = idx & 31;
        sA[kk][m] = Q [(size_t)(i0 + m) * HD + kk];
        sW[kk][m] = Kp[(size_t)(j0 + m) * HD + kk];
    }
    __syncthreads();

    float acc[4][4] = {};
#pragma unroll
    for (int kk = 0; kk < 32; kk++) {
        float a[4], w[4];
#pragma unroll
        for (int u = 0; u < 4; u++) { a[u] = sA[kk][ty*4 + u]; w[u] = sW[kk][tx*4 + u]; }
#pragma unroll
        for (int u = 0; u < 4; u++)
#pragma unroll
            for (int v = 0; v < 4; v++)
                acc[u][v] = fmaf(a[u], w[v], acc[u][v]);
    }

    const float scale = 0.1767766952966369f; // 1/sqrt(32)
#pragma unroll
    for (int u = 0; u < 4; u++) {
        int row = i0 + ty*4 + u;
#pragma unroll
        for (int v = 0; v < 4; v++)
            C[(size_t)row * LL + (j0 + tx*4 + v)] = acc[u][v] * scale;
    }
}

// =========================================================================
// K3: softmax + head-mean.  One block per (b,i); warp h owns head h's row.
// Row of 512 lives in 16 regs/lane; shfl reductions; ONE __syncthreads().
// =========================================================================
__global__ __launch_bounds__(256) void softmax_mean_kernel(float* __restrict__ out)
{
    const int b = blockIdx.x >> 9;
    const int i = blockIdx.x & 511;
    const int wid  = threadIdx.x >> 5;
    const int lane = threadIdx.x & 31;

    __shared__ float p[8][512];

    const float* row = g_logits + ((size_t)(b*8 + wid) * LL + i) * LL;

    float v[16];
    float mx = -1e30f;
#pragma unroll
    for (int r = 0; r < 16; r++) {
        v[r] = row[lane + 32*r];
        mx = fmaxf(mx, v[r]);
    }
#pragma unroll
    for (int o = 16; o; o >>= 1) mx = fmaxf(mx, __shfl_xor_sync(0xffffffffu, mx, o));

    float s = 0.0f;
#pragma unroll
    for (int r = 0; r < 16; r++) { v[r] = __expf(v[r] - mx); s += v[r]; }
#pragma unroll
    for (int o = 16; o; o >>= 1) s += __shfl_xor_sync(0xffffffffu, s, o);
    const float inv = 1.0f / s;

#pragma unroll
    for (int r = 0; r < 16; r++) p[wid][lane + 32*r] = v[r] * inv;

    __syncthreads();

    const int t = threadIdx.x;
    const size_t o = ((size_t)b * LL + i) * LL;
#pragma unroll
    for (int jj = 0; jj < 2; jj++) {
        int j = t + jj * 256;
        float a = 0.0f;
#pragma unroll
        for (int h = 0; h < 8; h++) a += p[h][j];
        out[o + j] = a * 0.125f;
    }
}

// =========================================================================
// K4: match_scores[b,i,j] = sigmoid( sum_c relu(h1[b,i,c]+h2[b,j,c]) * w2[c] + b2 )
// 64x64 tiles, 512 threads, 4x2 per thread.
// A-read = broadcast LDS.128, B-read = conflict-free LDS.64.
// =========================================================================
__global__ __launch_bounds__(512) void match_kernel(
    const float* __restrict__ W2, const float* __restrict__ b2,
    float* __restrict__ out)
{
    const int b  = blockIdx.z;
    const int i0 = blockIdx.y * 64;
    const int j0 = blockIdx.x * 64;

    const float* A  = g_h1 + (size_t)b * LL * HD;
    const float* Bm = g_h2 + (size_t)b * LL * HD;

    __shared__ float sA[32][68];   // [kk][m], stride 68 -> float4 aligned
    __shared__ float sB[32][68];
    __shared__ float sw2[HD];

    const int tid = threadIdx.x;
    const int ty = tid >> 5;       // 0..15 -> i group of 4
    const int tx = tid & 31;       // 0..31 -> j group of 2

    if (tid < HD) sw2[tid] = W2[tid];

    // loader: each thread brings one float4 of A and one of B per chunk
    const int lm  = tid >> 3;        // 0..63
    const int lk4 = (tid & 7) * 4;   // 0,4,...,28

    float acc[4][2] = {};

    for (int k0 = 0; k0 < HD; k0 += 32) {
        float4 va = *(const float4*)&A [(size_t)(i0 + lm) * HD + k0 + lk4];
        float4 vb = *(const float4*)&Bm[(size_t)(j0 + lm) * HD + k0 + lk4];
        __syncthreads();
        sA[lk4+0][lm] = va.x; sA[lk4+1][lm] = va.y; sA[lk4+2][lm] = va.z; sA[lk4+3][lm] = va.w;
        sB[lk4+0][lm] = vb.x; sB[lk4+1][lm] = vb.y; sB[lk4+2][lm] = vb.z; sB[lk4+3][lm] = vb.w;
        __syncthreads();

#pragma unroll
        for (int kk = 0; kk < 32; kk++) {
            const float4 a  = *(const float4*)&sA[kk][ty*4];   // warp broadcast
            const float2 bb = *(const float2*)&sB[kk][tx*2];   // conflict-free
            const float  w  = sw2[k0 + kk];
            acc[0][0] = fmaf(fmaxf(a.x + bb.x, 0.0f), w, acc[0][0]);
            acc[0][1] = fmaf(fmaxf(a.x + bb.y, 0.0f), w, acc[0][1]);
            acc[1][0] = fmaf(fmaxf(a.y + bb.x, 0.0f), w, acc[1][0]);
            acc[1][1] = fmaf(fmaxf(a.y + bb.y, 0.0f), w, acc[1][1]);
            acc[2][0] = fmaf(fmaxf(a.z + bb.x, 0.0f), w, acc[2][0]);
            acc[2][1] = fmaf(fmaxf(a.z + bb.y, 0.0f), w, acc[2][1]);
            acc[3][0] = fmaf(fmaxf(a.w + bb.x, 0.0f), w, acc[3][0]);
            acc[3][1] = fmaf(fmaxf(a.w + bb.y, 0.0f), w, acc[3][1]);
        }
    }

    const float bias2 = b2[0];
    const size_t base = (size_t)BB * LL * LL + (size_t)b * LL * LL;
#pragma unroll
    for (int u = 0; u < 4; u++) {
        const int row = i0 + ty*4 + u;
        float2 o2;
        o2.x = 1.0f / (1.0f + __expf(-(acc[u][0] + bias2)));
        o2.y = 1.0f / (1.0f + __expf(-(acc[u][1] + bias2)));
        *(float2*)&out[base + (size_t)row * LL + (j0 + tx*2)] = o2;
    }
}

// =========================================================================
extern "C" void kernel_launch(void* const* d_in, const int* in_sizes, int n_in,
                              void* d_out, int out_size)
{
    const float* e1  = (const float*)d_in[0];  // (B,L1,H)
    const float* e2  = (const float*)d_in[1];  // (B,L2,H)
    const float* ipw = (const float*)d_in[2];  // (3H,H)
    const float* ipb = (const float*)d_in[3];  // (3H,)
    const float* W1  = (const float*)d_in[4];  // (H,2H)
    const float* b1  = (const float*)d_in[5];  // (H,)
    const float* W2  = (const float*)d_in[6];  // (1,H)
    const float* b2  = (const float*)d_in[7];  // (1,)
    float* out = (float*)d_out;                // [attn (B,L1,L2)] ++ [match (B,L1,L2)]

    proj_kernel   <<<dim3(HD/64, (BB*LL)/64, 4), 256>>>(e1, e2, ipw, ipb, W1, b1);
    logits_kernel <<<dim3(LL/64, LL/64, BB*NHEAD), 256>>>();
    softmax_mean_kernel<<<BB*LL, 256>>>(out);
    match_kernel  <<<dim3(LL/64, LL/64, BB), 512>>>(W2, b2, out);
}

// round 4
// speedup vs baseline: 1.2702x; 1.1196x over previous
#include <cuda_runtime.h>
#include <math.h>

#define HD 256      // hidden dim
#define BB 2        // batch
#define LL 512      // seq len (L1 == L2)
#define NHEAD 8
#define DHEAD 32

// ---------------- scratch (device globals; no allocation) ----------------
__device__ float g_q [BB*LL*HD];                 // 1 MB
__device__ float g_k [BB*LL*HD];                 // 1 MB
__device__ float g_h1[BB*LL*HD];                 // 1 MB (includes +b1)
__device__ float g_h2[BB*LL*HD];                 // 1 MB
__device__ float g_logits[(size_t)BB*NHEAD*LL*LL]; // 16 MB

// ---------------- packed fp32x2 helpers (Blackwell) ----------------
typedef unsigned long long u64p;

__device__ __forceinline__ u64p f2_pack(float lo, float hi) {
    u64p r; asm("mov.b64 %0, {%1, %2};" : "=l"(r) : "f"(lo), "f"(hi)); return r;
}
__device__ __forceinline__ void f2_unpack(u64p p, float& lo, float& hi) {
    asm("mov.b64 {%0, %1}, %2;" : "=f"(lo), "=f"(hi) : "l"(p));
}
__device__ __forceinline__ u64p f2_fma(u64p a, u64p b, u64p c) {
    u64p d; asm("fma.rn.f32x2 %0, %1, %2, %3;" : "=l"(d) : "l"(a), "l"(b), "l"(c)); return d;
}
__device__ __forceinline__ u64p f2_add(u64p a, u64p b) {
    u64p d; asm("add.rn.f32x2 %0, %1, %2;" : "=l"(d) : "l"(a), "l"(b)); return d;
}
__device__ __forceinline__ u64p f2_relu(u64p x) {
    float lo, hi; f2_unpack(x, lo, hi);
    return f2_pack(fmaxf(lo, 0.0f), fmaxf(hi, 0.0f));
}

// =========================================================================
// K1: projections.  job z: 0=q(e1,Wq,bq) 1=k(e2,Wk,bk) 2=h1(e1,W1a,b1) 3=h2(e2,W1b,0)
// C[m,o] = sum_c A[m,c]*W[o*ldw + c] (+ bias[o]);  M=1024, N=256, K=256
// 64x64 tile, 256 threads, 4x4/thread, FFMA2-packed along the o-dim.
// =========================================================================
__global__ __launch_bounds__(256) void proj_kernel(
    const float* __restrict__ e1, const float* __restrict__ e2,
    const float* __restrict__ ipw, const float* __restrict__ ipb,
    const float* __restrict__ W1,  const float* __restrict__ b1)
{
    const int job = blockIdx.z;
    const float* A; const float* W; const float* bias; int ldw; float* C;
    if (job == 0)      { A = e1; W = ipw;           bias = ipb;      ldw = HD;   C = g_q;  }
    else if (job == 1) { A = e2; W = ipw + HD*HD;   bias = ipb + HD; ldw = HD;   C = g_k;  }
    else if (job == 2) { A = e1; W = W1;            bias = b1;       ldw = 2*HD; C = g_h1; }
    else               { A = e2; W = W1 + HD;       bias = nullptr;  ldw = 2*HD; C = g_h2; }

    const int i0 = blockIdx.y * 64;
    const int j0 = blockIdx.x * 64;

    __shared__ float sA[32][68];
    __shared__ float sW[32][68];

    const int tid = threadIdx.x;
    const int tx = tid & 15, ty = tid >> 4;

    u64p acc[4][2] = {};   // 4 rows x (2 packed col-pairs) = 4x4 scalars

    for (int k0 = 0; k0 < HD; k0 += 32) {
#pragma unroll
        for (int r = 0; r < 8; r++) {
            int idx = r * 256 + tid;
            int m = idx >> 5, kk = idx & 31;
            sA[kk][m] = A[(size_t)(i0 + m) * HD  + k0 + kk];
            sW[kk][m] = W[(size_t)(j0 + m) * ldw + k0 + kk];
        }
        __syncthreads();
#pragma unroll
        for (int kk = 0; kk < 32; kk++) {
            const float4 a4 = *(const float4*)&sA[kk][ty*4];
            const ulonglong2 wp = *(const ulonglong2*)&sW[kk][tx*4];
            u64p ad0 = f2_pack(a4.x, a4.x);
            u64p ad1 = f2_pack(a4.y, a4.y);
            u64p ad2 = f2_pack(a4.z, a4.z);
            u64p ad3 = f2_pack(a4.w, a4.w);
            acc[0][0] = f2_fma(ad0, wp.x, acc[0][0]);
            acc[0][1] = f2_fma(ad0, wp.y, acc[0][1]);
            acc[1][0] = f2_fma(ad1, wp.x, acc[1][0]);
            acc[1][1] = f2_fma(ad1, wp.y, acc[1][1]);
            acc[2][0] = f2_fma(ad2, wp.x, acc[2][0]);
            acc[2][1] = f2_fma(ad2, wp.y, acc[2][1]);
            acc[3][0] = f2_fma(ad3, wp.x, acc[3][0]);
            acc[3][1] = f2_fma(ad3, wp.y, acc[3][1]);
        }
        __syncthreads();
    }

    float bv[4] = {0.f, 0.f, 0.f, 0.f};
    if (bias) {
#pragma unroll
        for (int v = 0; v < 4; v++) bv[v] = bias[j0 + tx*4 + v];
    }
#pragma unroll
    for (int u = 0; u < 4; u++) {
        float c0, c1, c2, c3;
        f2_unpack(acc[u][0], c0, c1);
        f2_unpack(acc[u][1], c2, c3);
        float4 o4 = make_float4(c0 + bv[0], c1 + bv[1], c2 + bv[2], c3 + bv[3]);
        *(float4*)&C[(size_t)(i0 + ty*4 + u) * HD + j0 + tx*4] = o4;
    }
}

// =========================================================================
// K2: logits[b,h,i,j] = (1/sqrt(32)) * sum_d q[b,i,h*32+d]*k[b,j,h*32+d]
// grid (8,8,16); 64x64 tile, K=32, FFMA2-packed.
// =========================================================================
__global__ __launch_bounds__(256) void logits_kernel()
{
    const int bh = blockIdx.z;
    const int b  = bh >> 3, h = bh & 7;
    const float* Q  = g_q + (size_t)b * LL * HD + h * DHEAD;
    const float* Kp = g_k + (size_t)b * LL * HD + h * DHEAD;
    float* C = g_logits + (size_t)bh * LL * LL;

    const int i0 = blockIdx.y * 64;
    const int j0 = blockIdx.x * 64;

    __shared__ float sA[32][68];
    __shared__ float sW[32][68];

    const int tid = threadIdx.x;
    const int tx = tid & 15, ty = tid >> 4;

#pragma unroll
    for (int r = 0; r < 8; r++) {
        int idx = r * 256 + tid;
        int m = idx >> 5, kk = idx & 31;
        sA[kk][m] = Q [(size_t)(i0 + m) * HD + kk];
        sW[kk][m] = Kp[(size_t)(j0 + m) * HD + kk];
    }
    __syncthreads();

    u64p acc[4][2] = {};
#pragma unroll
    for (int kk = 0; kk < 32; kk++) {
        const float4 a4 = *(const float4*)&sA[kk][ty*4];
        const ulonglong2 wp = *(const ulonglong2*)&sW[kk][tx*4];
        u64p ad0 = f2_pack(a4.x, a4.x);
        u64p ad1 = f2_pack(a4.y, a4.y);
        u64p ad2 = f2_pack(a4.z, a4.z);
        u64p ad3 = f2_pack(a4.w, a4.w);
        acc[0][0] = f2_fma(ad0, wp.x, acc[0][0]);
        acc[0][1] = f2_fma(ad0, wp.y, acc[0][1]);
        acc[1][0] = f2_fma(ad1, wp.x, acc[1][0]);
        acc[1][1] = f2_fma(ad1, wp.y, acc[1][1]);
        acc[2][0] = f2_fma(ad2, wp.x, acc[2][0]);
        acc[2][1] = f2_fma(ad2, wp.y, acc[2][1]);
        acc[3][0] = f2_fma(ad3, wp.x, acc[3][0]);
        acc[3][1] = f2_fma(ad3, wp.y, acc[3][1]);
    }

    const float scale = 0.1767766952966369f; // 1/sqrt(32)
#pragma unroll
    for (int u = 0; u < 4; u++) {
        float c0, c1, c2, c3;
        f2_unpack(acc[u][0], c0, c1);
        f2_unpack(acc[u][1], c2, c3);
        float4 o4 = make_float4(c0*scale, c1*scale, c2*scale, c3*scale);
        *(float4*)&C[(size_t)(i0 + ty*4 + u) * LL + j0 + tx*4] = o4;
    }
}

// =========================================================================
// K3: softmax + head-mean.  One block per (b,i); warp h owns head h's row.
// =========================================================================
__global__ __launch_bounds__(256) void softmax_mean_kernel(float* __restrict__ out)
{
    const int b = blockIdx.x >> 9;
    const int i = blockIdx.x & 511;
    const int wid  = threadIdx.x >> 5;
    const int lane = threadIdx.x & 31;

    __shared__ float p[8][512];

    const float* row = g_logits + ((size_t)(b*8 + wid) * LL + i) * LL;

    float v[16];
    float mx = -1e30f;
#pragma unroll
    for (int r = 0; r < 16; r++) {
        v[r] = row[lane + 32*r];
        mx = fmaxf(mx, v[r]);
    }
#pragma unroll
    for (int o = 16; o; o >>= 1) mx = fmaxf(mx, __shfl_xor_sync(0xffffffffu, mx, o));

    float s = 0.0f;
#pragma unroll
    for (int r = 0; r < 16; r++) { v[r] = __expf(v[r] - mx); s += v[r]; }
#pragma unroll
    for (int o = 16; o; o >>= 1) s += __shfl_xor_sync(0xffffffffu, s, o);
    const float inv = 1.0f / s;

#pragma unroll
    for (int r = 0; r < 16; r++) p[wid][lane + 32*r] = v[r] * inv;

    __syncthreads();

    const int t = threadIdx.x;
    const size_t o = ((size_t)b * LL + i) * LL;
#pragma unroll
    for (int jj = 0; jj < 2; jj++) {
        int j = t + jj * 256;
        float a = 0.0f;
#pragma unroll
        for (int h = 0; h < 8; h++) a += p[h][j];
        out[o + j] = a * 0.125f;
    }
}

// =========================================================================
// K4: match_scores[b,i,j] = sigmoid( sum_c relu(h1[b,i,c]+h2[b,j,c]) * w2[c] + b2 )
// Tile 64(i) x 32(j), 256 threads -> grid 256 blocks.
// Per thread: 4i x 2j; pairs packed along i (FADD2/FFMA2), scalar FMNMX relu.
// =========================================================================
__global__ __launch_bounds__(256) void match_kernel(
    const float* __restrict__ W2, const float* __restrict__ b2,
    float* __restrict__ out)
{
    const int b  = blockIdx.z;
    const int i0 = blockIdx.y * 64;
    const int j0 = blockIdx.x * 32;

    const float* A  = g_h1 + (size_t)b * LL * HD;
    const float* Bm = g_h2 + (size_t)b * LL * HD;

    __shared__ float sA[32][68];   // [kk][i], 64 used
    __shared__ float sB[32][36];   // [kk][j], 32 used
    __shared__ float sw2[HD];

    const int tid = threadIdx.x;
    const int ty = tid >> 4;       // 0..15 -> i group of 4
    const int tx = tid & 15;       // 0..15 -> j group of 2

    sw2[tid] = W2[tid];            // tid < 256 == HD

    const int lmA = tid >> 3;        // 0..31
    const int lk4 = (tid & 7) * 4;   // 0,4,...,28

    u64p acc[2][2] = {};  // [i-pair][j] ; each holds rows (4*ty + 2p, 4*ty + 2p+1)

    for (int k0 = 0; k0 < HD; k0 += 32) {
        float4 va0 = *(const float4*)&A [(size_t)(i0 + lmA)      * HD + k0 + lk4];
        float4 va1 = *(const float4*)&A [(size_t)(i0 + 32 + lmA) * HD + k0 + lk4];
        float4 vb  = *(const float4*)&Bm[(size_t)(j0 + lmA)      * HD + k0 + lk4];
        __syncthreads();
        sA[lk4+0][lmA] = va0.x; sA[lk4+1][lmA] = va0.y; sA[lk4+2][lmA] = va0.z; sA[lk4+3][lmA] = va0.w;
        sA[lk4+0][32+lmA] = va1.x; sA[lk4+1][32+lmA] = va1.y; sA[lk4+2][32+lmA] = va1.z; sA[lk4+3][32+lmA] = va1.w;
        sB[lk4+0][lmA] = vb.x; sB[lk4+1][lmA] = vb.y; sB[lk4+2][lmA] = vb.z; sB[lk4+3][lmA] = vb.w;
        __syncthreads();

#pragma unroll
        for (int kk = 0; kk < 32; kk++) {
            const ulonglong2 ap = *(const ulonglong2*)&sA[kk][ty*4];  // 2 i-pairs
            const float bx = sB[kk][tx*2];
            const float by = sB[kk][tx*2+1];
            const float w  = sw2[k0 + kk];
            const u64p bxd = f2_pack(bx, bx);
            const u64p byd = f2_pack(by, by);
            const u64p wd  = f2_pack(w, w);
            acc[0][0] = f2_fma(f2_relu(f2_add(ap.x, bxd)), wd, acc[0][0]);
            acc[0][1] = f2_fma(f2_relu(f2_add(ap.x, byd)), wd, acc[0][1]);
            acc[1][0] = f2_fma(f2_relu(f2_add(ap.y, bxd)), wd, acc[1][0]);
            acc[1][1] = f2_fma(f2_relu(f2_add(ap.y, byd)), wd, acc[1][1]);
        }
    }

    const float bias2 = b2[0];
    const size_t base = (size_t)BB * LL * LL + (size_t)b * LL * LL;

    float s00, s10, s01, s11, s20, s30, s21, s31;
    f2_unpack(acc[0][0], s00, s10);   // col tx*2+0, rows ty*4+0, ty*4+1
    f2_unpack(acc[0][1], s01, s11);   // col tx*2+1, rows ty*4+0, ty*4+1
    f2_unpack(acc[1][0], s20, s30);   // col tx*2+0, rows ty*4+2, ty*4+3
    f2_unpack(acc[1][1], s21, s31);   // col tx*2+1, rows ty*4+2, ty*4+3

    const int col = j0 + tx*2;
    const int r0  = i0 + ty*4;
    float2 o0 = make_float2(1.0f/(1.0f+__expf(-(s00+bias2))), 1.0f/(1.0f+__expf(-(s01+bias2))));
    float2 o1 = make_float2(1.0f/(1.0f+__expf(-(s10+bias2))), 1.0f/(1.0f+__expf(-(s11+bias2))));
    float2 o2 = make_float2(1.0f/(1.0f+__expf(-(s20+bias2))), 1.0f/(1.0f+__expf(-(s21+bias2))));
    float2 o3 = make_float2(1.0f/(1.0f+__expf(-(s30+bias2))), 1.0f/(1.0f+__expf(-(s31+bias2))));
    *(float2*)&out[base + (size_t)(r0+0) * LL + col] = o0;
    *(float2*)&out[base + (size_t)(r0+1) * LL + col] = o1;
    *(float2*)&out[base + (size_t)(r0+2) * LL + col] = o2;
    *(float2*)&out[base + (size_t)(r0+3) * LL + col] = o3;
}

// =========================================================================
extern "C" void kernel_launch(void* const* d_in, const int* in_sizes, int n_in,
                              void* d_out, int out_size)
{
    const float* e1  = (const float*)d_in[0];  // (B,L1,H)
    const float* e2  = (const float*)d_in[1];  // (B,L2,H)
    const float* ipw = (const float*)d_in[2];  // (3H,H)
    const float* ipb = (const float*)d_in[3];  // (3H,)
    const float* W1  = (const float*)d_in[4];  // (H,2H)
    const float* b1  = (const float*)d_in[5];  // (H,)
    const float* W2  = (const float*)d_in[6];  // (1,H)
    const float* b2  = (const float*)d_in[7];  // (1,)
    float* out = (float*)d_out;                // [attn (B,L1,L2)] ++ [match (B,L1,L2)]

    proj_kernel   <<<dim3(HD/64, (BB*LL)/64, 4), 256>>>(e1, e2, ipw, ipb, W1, b1);
    logits_kernel <<<dim3(LL/64, LL/64, BB*NHEAD), 256>>>();
    softmax_mean_kernel<<<BB*LL, 256>>>(out);
    match_kernel  <<<dim3(LL/32, LL/64, BB), 256>>>(W2, b2, out);
}